// round 2
// baseline (speedup 1.0000x reference)
#include <cuda_runtime.h>
#include <math.h>

#define NROWS 4096
#define DIMS  512
#define BM    128
#define BK    16
#define TILES (NROWS / BM)   // 32
#define NTH   512

// Scratch (no dynamic allocation allowed)
__device__ float g_sqX[NROWS];
__device__ float g_sqY[NROWS];
__device__ float g_rA[NROWS];             // row sums of centered-input kernel A (from X)
__device__ float g_rB[NROWS];             // row sums for B (from Y)
__device__ float g_t1p[TILES * TILES];    // per-block partial of sum(A .* B)

// ---------------------------------------------------------------------------
// Kernel 1: per-row squared norms + zero the row-sum accumulators
// ---------------------------------------------------------------------------
__global__ void prep_kernel(const float* __restrict__ X, const float* __restrict__ Y) {
    int row = blockIdx.x;
    int t = threadIdx.x;          // 128 threads, 4 floats each (512 dims)
    const float4* xr = reinterpret_cast<const float4*>(X + (size_t)row * DIMS);
    const float4* yr = reinterpret_cast<const float4*>(Y + (size_t)row * DIMS);
    float4 xv = xr[t];
    float4 yv = yr[t];
    float sx = xv.x*xv.x + xv.y*xv.y + xv.z*xv.z + xv.w*xv.w;
    float sy = yv.x*yv.x + yv.y*yv.y + yv.z*yv.z + yv.w*yv.w;
    #pragma unroll
    for (int o = 16; o > 0; o >>= 1) {
        sx += __shfl_xor_sync(0xffffffffu, sx, o);
        sy += __shfl_xor_sync(0xffffffffu, sy, o);
    }
    __shared__ float wx[4], wy[4];
    if ((t & 31) == 0) { wx[t >> 5] = sx; wy[t >> 5] = sy; }
    __syncthreads();
    if (t == 0) {
        g_sqX[row] = wx[0] + wx[1] + wx[2] + wx[3];
        g_sqY[row] = wy[0] + wy[1] + wy[2] + wy[3];
        g_rA[row] = 0.f;
        g_rB[row] = 0.f;
    }
}

// ---------------------------------------------------------------------------
// Tile GEMM pass: acc[m][n] += sum_k M[i,k]*M[j,k] for one 128x128 tile
// ---------------------------------------------------------------------------
__device__ __forceinline__ void gemm_tile(
    const float* __restrict__ M, int ibase, int jbase,
    float (&acc)[8][4], float (*As)[BM], float (*Bs)[BM],
    int tid, int tx, int ty)
{
    int lr = tid >> 2;    // 0..127 : tile row to load
    int lq = tid & 3;     // 0..3   : k-quarter
    #pragma unroll 1
    for (int k0 = 0; k0 < DIMS; k0 += BK) {
        float4 av = *reinterpret_cast<const float4*>(M + (ibase + lr) * DIMS + k0 + lq * 4);
        float4 bv = *reinterpret_cast<const float4*>(M + (jbase + lr) * DIMS + k0 + lq * 4);
        __syncthreads();   // previous iteration's reads must finish before overwrite
        As[lq*4+0][lr] = av.x; As[lq*4+1][lr] = av.y; As[lq*4+2][lr] = av.z; As[lq*4+3][lr] = av.w;
        Bs[lq*4+0][lr] = bv.x; Bs[lq*4+1][lr] = bv.y; Bs[lq*4+2][lr] = bv.z; Bs[lq*4+3][lr] = bv.w;
        __syncthreads();
        #pragma unroll
        for (int kk = 0; kk < BK; kk++) {
            float4 a0 = *reinterpret_cast<const float4*>(&As[kk][ty * 8]);
            float4 a1 = *reinterpret_cast<const float4*>(&As[kk][ty * 8 + 4]);
            float4 b  = *reinterpret_cast<const float4*>(&Bs[kk][tx * 4]);
            float am[8] = {a0.x, a0.y, a0.z, a0.w, a1.x, a1.y, a1.z, a1.w};
            float bn[4] = {b.x, b.y, b.z, b.w};
            #pragma unroll
            for (int m = 0; m < 8; m++)
                #pragma unroll
                for (int n = 0; n < 4; n++)
                    acc[m][n] += am[m] * bn[n];
        }
    }
    __syncthreads();  // smem will be reused by the next pass
}

// Convert Gram values to RBF kernel values in place.
// arg = g - 0.5*sq_i - 0.5*sq_j ; value = exp(arg), 0 when it underflows.
// Returns warp-uniform "this warp has any non-underflowed value".
__device__ __forceinline__ bool to_kernel_vals(
    float (&acc)[8][4], const float* __restrict__ sq, int gi0, int gj0)
{
    float hi[8], hj[4];
    #pragma unroll
    for (int m = 0; m < 8; m++) hi[m] = 0.5f * sq[gi0 + m];
    #pragma unroll
    for (int n = 0; n < 4; n++) hj[n] = 0.5f * sq[gj0 + n];
    float mx = -1e30f;
    #pragma unroll
    for (int m = 0; m < 8; m++)
        #pragma unroll
        for (int n = 0; n < 4; n++) {
            float arg = acc[m][n] - hi[m] - hj[n];
            acc[m][n] = arg;
            mx = fmaxf(mx, arg);
        }
    bool need = (__ballot_sync(0xffffffffu, mx > -87.f) != 0u);
    if (need) {
        #pragma unroll
        for (int m = 0; m < 8; m++)
            #pragma unroll
            for (int n = 0; n < 4; n++)
                acc[m][n] = (acc[m][n] > -87.f) ? __expf(acc[m][n]) : 0.f;
    }
    return need;
}

// ---------------------------------------------------------------------------
// Kernel 2: fused upper-triangular tile pass
// ---------------------------------------------------------------------------
__global__ __launch_bounds__(NTH, 1)
void hsic_main_kernel(const float* __restrict__ X, const float* __restrict__ Y) {
    int bi = blockIdx.y, bj = blockIdx.x;
    int bid = bi * TILES + bj;
    if (bj < bi) {                       // lower triangle: contribute a clean zero partial
        if (threadIdx.x == 0) g_t1p[bid] = 0.f;
        return;
    }
    __shared__ float As[BK][BM];
    __shared__ float Bs[BK][BM];
    __shared__ float wsum[NTH / 32];

    int tid = threadIdx.x;
    int tx = tid & 31;                   // 32 column groups of 4
    int ty = tid >> 5;                   // 16 row groups of 8
    int ibase = bi * BM, jbase = bj * BM;
    int gi0 = ibase + ty * 8;
    int gj0 = jbase + tx * 4;

    float accX[8][4], accY[8][4];
    #pragma unroll
    for (int m = 0; m < 8; m++)
        #pragma unroll
        for (int n = 0; n < 4; n++) { accX[m][n] = 0.f; accY[m][n] = 0.f; }

    gemm_tile(X, ibase, jbase, accX, As, Bs, tid, tx, ty);
    gemm_tile(Y, ibase, jbase, accY, As, Bs, tid, tx, ty);

    bool needx = to_kernel_vals(accX, g_sqX, gi0, gj0);
    bool needy = to_kernel_vals(accY, g_sqY, gi0, gj0);
    bool diag = (bi == bj);

    // Row sums (and column sums for strictly-upper tiles, via symmetry A_ji = A_ij).
    if (needx) {
        #pragma unroll
        for (int m = 0; m < 8; m++) {
            float r = accX[m][0] + accX[m][1] + accX[m][2] + accX[m][3];
            #pragma unroll
            for (int o = 16; o > 0; o >>= 1) r += __shfl_xor_sync(0xffffffffu, r, o);
            if (tx == 0) atomicAdd(&g_rA[gi0 + m], r);
        }
        if (!diag) {
            #pragma unroll
            for (int n = 0; n < 4; n++) {
                float c = 0.f;
                #pragma unroll
                for (int m = 0; m < 8; m++) c += accX[m][n];
                atomicAdd(&g_rA[gj0 + n], c);
            }
        }
    }
    if (needy) {
        #pragma unroll
        for (int m = 0; m < 8; m++) {
            float r = accY[m][0] + accY[m][1] + accY[m][2] + accY[m][3];
            #pragma unroll
            for (int o = 16; o > 0; o >>= 1) r += __shfl_xor_sync(0xffffffffu, r, o);
            if (tx == 0) atomicAdd(&g_rB[gi0 + m], r);
        }
        if (!diag) {
            #pragma unroll
            for (int n = 0; n < 4; n++) {
                float c = 0.f;
                #pragma unroll
                for (int m = 0; m < 8; m++) c += accY[m][n];
                atomicAdd(&g_rB[gj0 + n], c);
            }
        }
    }

    // T1 partial: sum(A .* B) over this tile (x2 off-diagonal), deterministic per block.
    float p = 0.f;
    if (needx && needy) {
        #pragma unroll
        for (int m = 0; m < 8; m++)
            #pragma unroll
            for (int n = 0; n < 4; n++)
                p += accX[m][n] * accY[m][n];
    }
    #pragma unroll
    for (int o = 16; o > 0; o >>= 1) p += __shfl_xor_sync(0xffffffffu, p, o);
    if ((tid & 31) == 0) wsum[tid >> 5] = p;
    __syncthreads();
    if (tid == 0) {
        float s = 0.f;
        #pragma unroll
        for (int w = 0; w < NTH / 32; w++) s += wsum[w];
        g_t1p[bid] = diag ? s : 2.f * s;
    }
}

// ---------------------------------------------------------------------------
// Kernel 3: final fixed-order reduction -> HSIC scalar
// ---------------------------------------------------------------------------
__global__ void hsic_final_kernel(float* __restrict__ out) {
    int t = threadIdx.x;   // 256 threads
    float t1 = 0.f, sa = 0.f, sb = 0.f, dab = 0.f;
    for (int b = t; b < TILES * TILES; b += 256) t1 += g_t1p[b];
    for (int i = t; i < NROWS; i += 256) {
        float a = g_rA[i], bb = g_rB[i];
        sa += a; sb += bb; dab += a * bb;
    }
    #pragma unroll
    for (int o = 16; o > 0; o >>= 1) {
        t1  += __shfl_xor_sync(0xffffffffu, t1,  o);
        sa  += __shfl_xor_sync(0xffffffffu, sa,  o);
        sb  += __shfl_xor_sync(0xffffffffu, sb,  o);
        dab += __shfl_xor_sync(0xffffffffu, dab, o);
    }
    __shared__ float s1[8], s2[8], s3[8], s4[8];
    if ((t & 31) == 0) { int w = t >> 5; s1[w] = t1; s2[w] = sa; s3[w] = sb; s4[w] = dab; }
    __syncthreads();
    if (t == 0) {
        float T1 = 0.f, SA = 0.f, SB = 0.f, DAB = 0.f;
        for (int w = 0; w < 8; w++) { T1 += s1[w]; SA += s2[w]; SB += s3[w]; DAB += s4[w]; }
        float n = (float)NROWS;
        float S = T1 - 2.f * DAB / n + SA * SB / (n * n);
        out[0] = S / ((n - 1.f) * (n - 1.f));
    }
}

// ---------------------------------------------------------------------------
extern "C" void kernel_launch(void* const* d_in, const int* in_sizes, int n_in,
                              void* d_out, int out_size) {
    const float* X = (const float*)d_in[0];
    const float* Y = (const float*)d_in[1];
    float* out = (float*)d_out;
    (void)in_sizes; (void)n_in; (void)out_size;

    prep_kernel<<<NROWS, 128>>>(X, Y);
    hsic_main_kernel<<<dim3(TILES, TILES), NTH>>>(X, Y);
    hsic_final_kernel<<<1, 256>>>(out);
}

// round 5
// speedup vs baseline: 5.4884x; 5.4884x over previous
#include <cuda_runtime.h>
#include <cuda_bf16.h>
#include <cstdint>
#include <math.h>

#define NROWS 4096
#define DIMS  512
#define TM    128
#define TILES (NROWS / TM)                 // 32
#define NPAIRS (TILES * (TILES + 1) / 2)   // 528
#define KC    64                           // K-chunk (bf16) = 128 bytes per row
#define NCH   (DIMS / KC)                  // 8

// ---------------- scratch (no dynamic allocation allowed) -------------------
__device__ __nv_bfloat16 g_Xb[NROWS * DIMS];
__device__ __nv_bfloat16 g_Yb[NROWS * DIMS];
__device__ float g_shX[NROWS];   // 0.5*||x_i||^2
__device__ float g_shY[NROWS];
__device__ float g_rA[NROWS];    // row sums of KX (init 1.0 = diagonal)
__device__ float g_rB[NROWS];
__device__ int   g_flag[TILES * TILES];
__device__ float g_t1corr;

// ---------------- helpers (baseline PTX only: sm_80+-class) -----------------
__device__ __forceinline__ uint32_t smem_u32(const void* p) {
    uint32_t a;
    asm("{ .reg .u64 t; cvta.to.shared.u64 t, %1; cvt.u32.u64 %0, t; }" : "=r"(a) : "l"(p));
    return a;
}
__device__ __forceinline__ void ldsm4(uint32_t& r0, uint32_t& r1, uint32_t& r2, uint32_t& r3, uint32_t addr) {
    asm volatile("ldmatrix.sync.aligned.m8n8.x4.shared.b16 {%0,%1,%2,%3}, [%4];"
                 : "=r"(r0), "=r"(r1), "=r"(r2), "=r"(r3) : "r"(addr));
}
__device__ __forceinline__ void mma16816(float* c, const uint32_t* a, const uint32_t* b) {
    asm volatile("mma.sync.aligned.m16n8k16.row.col.f32.bf16.bf16.f32 "
                 "{%0,%1,%2,%3}, {%4,%5,%6,%7}, {%8,%9}, {%0,%1,%2,%3};"
                 : "+f"(c[0]), "+f"(c[1]), "+f"(c[2]), "+f"(c[3])
                 : "r"(a[0]), "r"(a[1]), "r"(a[2]), "r"(a[3]), "r"(b[0]), "r"(b[1]));
}
#define CP16(sm, gm) asm volatile("cp.async.cg.shared.global [%0], [%1], 16;" :: "r"(sm), "l"(gm))
#define CP_COMMIT()  asm volatile("cp.async.commit_group;" ::: "memory")
#define CP_WAIT1()   asm volatile("cp.async.wait_group 1;" ::: "memory")
#define CP_WAIT0()   asm volatile("cp.async.wait_group 0;" ::: "memory")

// SW128 swizzle applied to (row*128 + colbyte), colbyte in [0,128)
__device__ __forceinline__ uint32_t swz(int row, int colbyte) {
    return (uint32_t)(row * 128 + (colbyte ^ ((row & 7) << 4)));
}

// ---------------- SMEM layout for screen kernel -----------------------------
#define SM_A0 0
#define SM_B0 16384
#define SM_A1 32768
#define SM_B1 49152
#define SM_HI 65536
#define SM_HJ (65536 + 512)
#define SM_TOT (65536 + 1024 + 64)

// ---------------------------------------------------------------------------
// Kernel 1: norms + bf16 conversion + accumulator init
// ---------------------------------------------------------------------------
__global__ void prep_kernel(const float* __restrict__ X, const float* __restrict__ Y) {
    int row = blockIdx.x;
    int t = threadIdx.x;  // 128 threads, 4 elems each
    const float4* xr = reinterpret_cast<const float4*>(X + (size_t)row * DIMS);
    const float4* yr = reinterpret_cast<const float4*>(Y + (size_t)row * DIMS);
    float4 xv = xr[t], yv = yr[t];
    float sx = xv.x * xv.x + xv.y * xv.y + xv.z * xv.z + xv.w * xv.w;
    float sy = yv.x * yv.x + yv.y * yv.y + yv.z * yv.z + yv.w * yv.w;
    __nv_bfloat162* xo = reinterpret_cast<__nv_bfloat162*>(g_Xb + (size_t)row * DIMS);
    __nv_bfloat162* yo = reinterpret_cast<__nv_bfloat162*>(g_Yb + (size_t)row * DIMS);
    xo[t * 2 + 0] = __floats2bfloat162_rn(xv.x, xv.y);
    xo[t * 2 + 1] = __floats2bfloat162_rn(xv.z, xv.w);
    yo[t * 2 + 0] = __floats2bfloat162_rn(yv.x, yv.y);
    yo[t * 2 + 1] = __floats2bfloat162_rn(yv.z, yv.w);
    #pragma unroll
    for (int o = 16; o > 0; o >>= 1) {
        sx += __shfl_xor_sync(0xffffffffu, sx, o);
        sy += __shfl_xor_sync(0xffffffffu, sy, o);
    }
    __shared__ float wx[4], wy[4];
    if ((t & 31) == 0) { wx[t >> 5] = sx; wy[t >> 5] = sy; }
    __syncthreads();
    if (t == 0) {
        g_shX[row] = 0.5f * (wx[0] + wx[1] + wx[2] + wx[3]);
        g_shY[row] = 0.5f * (wy[0] + wy[1] + wy[2] + wy[3]);
        g_rA[row] = 1.0f;
        g_rB[row] = 1.0f;
        if (row < TILES * TILES) g_flag[row] = 0;
        if (row == 0) g_t1corr = 0.f;
    }
}

// ---------------------------------------------------------------------------
// Kernel 2: bf16 mma.sync screening GEMM over upper-triangular tile pairs.
// grid.x = 2*NPAIRS (matrix 0 = X, 1 = Y), 256 threads = 8 warps (4m x 2n).
// Each warp computes a 32x64 sub-tile of the 128x128 Gram tile.
// ---------------------------------------------------------------------------
__global__ __launch_bounds__(256, 2)
void screen_kernel() {
    extern __shared__ char smem[];
    uint32_t sb = smem_u32(smem);
    int tid = threadIdx.x;
    int wid = tid >> 5;
    int l = tid & 31;
    int wm = wid >> 1;         // 0..3 : 32-row band
    int wn = wid & 1;          // 0..1 : 64-col band

    // decode (matrix, bi, bj)
    int m = (int)blockIdx.x / NPAIRS;
    int p = (int)blockIdx.x % NPAIRS;
    int bi = 0, rem = p;
    while (rem >= TILES - bi) { rem -= TILES - bi; bi++; }
    int bj = bi + rem;
    int ibase = bi * TM, jbase = bj * TM;
    bool diagtile = (bi == bj);

    const __nv_bfloat16* M = (m == 0) ? g_Xb : g_Yb;
    const float* SH = (m == 0) ? g_shX : g_shY;

    // global source bytes for this thread's copy slice: row r = tid/2, half h = tid&1
    int cr = tid >> 1, ch = tid & 1;
    const char* gA = reinterpret_cast<const char*>(M) + (size_t)(ibase + cr) * (DIMS * 2) + ch * 64;
    const char* gB = reinterpret_cast<const char*>(M) + (size_t)(jbase + cr) * (DIMS * 2) + ch * 64;
    const uint32_t abuf[2] = {SM_A0, SM_A1};
    const uint32_t bbuf[2] = {SM_B0, SM_B1};

    // issue chunk 0 and chunk 1
    #pragma unroll
    for (int c = 0; c < 2; c++) {
        #pragma unroll
        for (int i = 0; i < 4; i++) {
            uint32_t so = swz(cr, ch * 64 + i * 16);
            CP16(sb + abuf[c] + so, gA + c * 128 + i * 16);
            CP16(sb + bbuf[c] + so, gB + c * 128 + i * 16);
        }
        CP_COMMIT();
    }

    float acc[2][8][4];
    #pragma unroll
    for (int mt = 0; mt < 2; mt++)
        #pragma unroll
        for (int nt = 0; nt < 8; nt++)
            #pragma unroll
            for (int q = 0; q < 4; q++) acc[mt][nt][q] = 0.f;

    #pragma unroll 1
    for (int c = 0; c < NCH; c++) {
        if (c < NCH - 1) CP_WAIT1(); else CP_WAIT0();
        __syncthreads();
        uint32_t ab = sb + abuf[c & 1];
        uint32_t bb = sb + bbuf[c & 1];
        #pragma unroll
        for (int ks = 0; ks < 4; ks++) {
            uint32_t a[2][4];
            #pragma unroll
            for (int mt = 0; mt < 2; mt++) {
                int row = wm * 32 + mt * 16 + (l & 15);
                int col = ks * 32 + ((l >> 4) << 4);
                ldsm4(a[mt][0], a[mt][1], a[mt][2], a[mt][3], ab + swz(row, col));
            }
            #pragma unroll
            for (int np = 0; np < 4; np++) {
                int row = wn * 64 + np * 16 + (l & 7) + ((l >> 4) & 1) * 8;
                int col = ks * 32 + ((l >> 3) & 1) * 16;
                uint32_t b[4];
                ldsm4(b[0], b[1], b[2], b[3], bb + swz(row, col));
                #pragma unroll
                for (int mt = 0; mt < 2; mt++) {
                    mma16816(acc[mt][np * 2],     a[mt], b);
                    mma16816(acc[mt][np * 2 + 1], a[mt], b + 2);
                }
            }
        }
        __syncthreads();
        if (c + 2 < NCH) {
            #pragma unroll
            for (int i = 0; i < 4; i++) {
                uint32_t so = swz(cr, ch * 64 + i * 16);
                CP16(sb + abuf[c & 1] + so, gA + (c + 2) * 128 + i * 16);
                CP16(sb + bbuf[c & 1] + so, gB + (c + 2) * 128 + i * 16);
            }
            CP_COMMIT();
        }
    }

    // stage 0.5*||.||^2 for rows and cols of this tile
    float* hiS = reinterpret_cast<float*>(smem + SM_HI);
    float* hjS = reinterpret_cast<float*>(smem + SM_HJ);
    if (tid < TM) {
        hiS[tid] = SH[ibase + tid];
        hjS[tid] = SH[jbase + tid];
    }
    __syncthreads();

    // epilogue: arg = g - hi - hj ; tile max excluding the true diagonal
    float mx = -1e30f;
    #pragma unroll
    for (int mt = 0; mt < 2; mt++) {
        int lr0 = wm * 32 + mt * 16 + (l >> 2);     // local rows lr0, lr0+8
        #pragma unroll
        for (int nt = 0; nt < 8; nt++) {
            int lc0 = wn * 64 + nt * 8 + (l & 3) * 2;
            #pragma unroll
            for (int q = 0; q < 4; q++) {
                int lr = lr0 + ((q >> 1) << 3);
                int lc = lc0 + (q & 1);
                float arg = acc[mt][nt][q] - hiS[lr] - hjS[lc];
                bool isdiag = diagtile && (lr == lc);
                if (!isdiag) mx = fmaxf(mx, arg);
            }
        }
    }
    #pragma unroll
    for (int o = 16; o > 0; o >>= 1) mx = fmaxf(mx, __shfl_xor_sync(0xffffffffu, mx, o));
    __shared__ float wmx[8];
    if (l == 0) wmx[wid] = mx;
    __syncthreads();
    if (tid == 0) {
        float bm = wmx[0];
        #pragma unroll
        for (int w = 1; w < 8; w++) bm = fmaxf(bm, wmx[w]);
        // bf16 screen error in arg is <~ +/-3; true survivors need arg > -87.
        if (bm > -78.f) g_flag[bi * TILES + bj] = 1;
    }
}

// ---------------------------------------------------------------------------
// Kernel 3: exact fp32 fallback for flagged tiles (expected: none flagged)
// ---------------------------------------------------------------------------
__global__ void fallback_kernel(const float* __restrict__ X, const float* __restrict__ Y) {
    int p = (int)blockIdx.x;
    int bi = 0, rem = p;
    while (rem >= TILES - bi) { rem -= TILES - bi; bi++; }
    int bj = bi + rem;
    if (g_flag[bi * TILES + bj] == 0) return;

    int ibase = bi * TM, jbase = bj * TM;
    for (int e = threadIdx.x; e < TM * TM; e += blockDim.x) {
        int li = e >> 7, lj = e & 127;
        int gi = ibase + li, gj = jbase + lj;
        if (gi >= gj) continue;   // strict upper only (diag handled analytically)
        const float4* xi = reinterpret_cast<const float4*>(X + (size_t)gi * DIMS);
        const float4* xj = reinterpret_cast<const float4*>(X + (size_t)gj * DIMS);
        const float4* yi = reinterpret_cast<const float4*>(Y + (size_t)gi * DIMS);
        const float4* yj = reinterpret_cast<const float4*>(Y + (size_t)gj * DIMS);
        float dx = 0.f, dy = 0.f;
        for (int k = 0; k < DIMS / 4; k++) {
            float4 a = xi[k], b = xj[k], c = yi[k], d = yj[k];
            dx += a.x * b.x + a.y * b.y + a.z * b.z + a.w * b.w;
            dy += c.x * d.x + c.y * d.y + c.z * d.z + c.w * d.w;
        }
        float ax = dx - g_shX[gi] - g_shX[gj];
        float ay = dy - g_shY[gi] - g_shY[gj];
        float ex = (ax > -87.f) ? expf(ax) : 0.f;
        float ey = (ay > -87.f) ? expf(ay) : 0.f;
        if (ex != 0.f) { atomicAdd(&g_rA[gi], ex); atomicAdd(&g_rA[gj], ex); }
        if (ey != 0.f) { atomicAdd(&g_rB[gi], ey); atomicAdd(&g_rB[gj], ey); }
        if (ex != 0.f && ey != 0.f) atomicAdd(&g_t1corr, 2.f * ex * ey);
    }
}

// ---------------------------------------------------------------------------
// Kernel 4: final combine
// S = T1 - (2/n)*sum(rA.*rB) + (sum rA)(sum rB)/n^2 ; T1 = n + t1corr
// ---------------------------------------------------------------------------
__global__ void final_kernel(float* __restrict__ out) {
    int t = threadIdx.x;  // 256
    float sa = 0.f, sb = 0.f, dab = 0.f;
    for (int i = t; i < NROWS; i += 256) {
        float a = g_rA[i], b = g_rB[i];
        sa += a; sb += b; dab += a * b;
    }
    #pragma unroll
    for (int o = 16; o > 0; o >>= 1) {
        sa += __shfl_xor_sync(0xffffffffu, sa, o);
        sb += __shfl_xor_sync(0xffffffffu, sb, o);
        dab += __shfl_xor_sync(0xffffffffu, dab, o);
    }
    __shared__ float s1[8], s2[8], s3[8];
    if ((t & 31) == 0) { int w = t >> 5; s1[w] = sa; s2[w] = sb; s3[w] = dab; }
    __syncthreads();
    if (t == 0) {
        float SA = 0.f, SB = 0.f, DAB = 0.f;
        for (int w = 0; w < 8; w++) { SA += s1[w]; SB += s2[w]; DAB += s3[w]; }
        float n = (float)NROWS;
        float T1 = n + g_t1corr;
        float S = T1 - 2.f * DAB / n + SA * SB / (n * n);
        out[0] = S / ((n - 1.f) * (n - 1.f));
    }
}

// ---------------------------------------------------------------------------
extern "C" void kernel_launch(void* const* d_in, const int* in_sizes, int n_in,
                              void* d_out, int out_size) {
    const float* X = (const float*)d_in[0];
    const float* Y = (const float*)d_in[1];
    float* out = (float*)d_out;
    (void)in_sizes; (void)n_in; (void)out_size;

    cudaFuncSetAttribute(screen_kernel, cudaFuncAttributeMaxDynamicSharedMemorySize, SM_TOT);

    prep_kernel<<<NROWS, 128>>>(X, Y);
    screen_kernel<<<2 * NPAIRS, 256, SM_TOT>>>();
    fallback_kernel<<<NPAIRS, 256>>>(X, Y);
    final_kernel<<<1, 256>>>(out);
}